// round 7
// baseline (speedup 1.0000x reference)
#include <cuda_runtime.h>

// PixCorr: per-row Pearson correlation over [256, 196608] fp32 rows, then
// mean over rows. Persistent work-stealing kernel:
//   - 1024 segments (4 per row, 12288 float4 each); 148 CTAs (one per SM)
//     grab segments via an atomic ticket -> 98.8% load balance (vs 86.5%
//     for the 2-wave 256-CTA launch).
//   - per segment: plain (cached) float4 streaming loads, 5 running sums,
//     block-reduce, store 5 partials to g_part[seg] (keyed by segment id
//     -> deterministic output regardless of scheduling).
//   - last CTA (done-ticket) combines segments per row in fixed order,
//     computes corrs + mean, writes d_out[0], resets counters for replay.

#define NROWS    256
#define D_ELEMS  196608          // 3*256*256
#define NVEC     (D_ELEMS / 4)   // 49152 float4 per row
#define SEGS     4               // segments per row
#define NSEG     (NROWS * SEGS)  // 1024
#define SEGVEC   (NVEC / SEGS)   // 12288 float4 per segment
#define THREADS  1024
#define GRID     148
#define EPS      1e-6f

__device__ float        g_part[NSEG][5];
__device__ unsigned int g_work;   // segment ticket (zero-init)
__device__ unsigned int g_done;   // CTA completion ticket (zero-init)

__device__ __forceinline__ float warp_sum(float v) {
    v += __shfl_xor_sync(0xFFFFFFFFu, v, 16);
    v += __shfl_xor_sync(0xFFFFFFFFu, v, 8);
    v += __shfl_xor_sync(0xFFFFFFFFu, v, 4);
    v += __shfl_xor_sync(0xFFFFFFFFu, v, 2);
    v += __shfl_xor_sync(0xFFFFFFFFu, v, 1);
    return v;
}

__global__ __launch_bounds__(THREADS, 1)
void pixcorr_persistent_kernel(const float* __restrict__ preds,
                               const float* __restrict__ targets,
                               float* __restrict__ out) {
    __shared__ unsigned int s_t;
    __shared__ float sh[5][THREADS / 32];
    __shared__ int   s_is_last;
    const int lane = threadIdx.x & 31;
    const int wid  = threadIdx.x >> 5;

    for (;;) {
        if (threadIdx.x == 0) s_t = atomicAdd(&g_work, 1u);
        __syncthreads();
        const unsigned int t = s_t;
        __syncthreads();          // protect s_t from next iteration's write
        if (t >= NSEG) break;

        const int row = t >> 2;           // t / SEGS
        const int seg = t & (SEGS - 1);   // t % SEGS
        const size_t base = (size_t)row * D_ELEMS + (size_t)seg * (SEGVEC * 4);
        const float4* __restrict__ z4 =
            reinterpret_cast<const float4*>(targets + base);
        const float4* __restrict__ b4 =
            reinterpret_cast<const float4*>(preds + base);

        float sz = 0.f, sb = 0.f, szz = 0.f, sbb = 0.f, szb = 0.f;

        // 12 iterations per thread, coalesced 128-bit cached loads.
        #pragma unroll 4
        for (int i = threadIdx.x; i < SEGVEC; i += THREADS) {
            float4 zv = z4[i];
            float4 bv = b4[i];
            sz  += (zv.x + zv.y) + (zv.z + zv.w);
            sb  += (bv.x + bv.y) + (bv.z + bv.w);
            szz  = fmaf(zv.x, zv.x, fmaf(zv.y, zv.y, fmaf(zv.z, zv.z, fmaf(zv.w, zv.w, szz))));
            sbb  = fmaf(bv.x, bv.x, fmaf(bv.y, bv.y, fmaf(bv.z, bv.z, fmaf(bv.w, bv.w, sbb))));
            szb  = fmaf(zv.x, bv.x, fmaf(zv.y, bv.y, fmaf(zv.z, bv.z, fmaf(zv.w, bv.w, szb))));
        }

        sz  = warp_sum(sz);
        sb  = warp_sum(sb);
        szz = warp_sum(szz);
        sbb = warp_sum(sbb);
        szb = warp_sum(szb);

        if (lane == 0) {
            sh[0][wid] = sz;  sh[1][wid] = sb;
            sh[2][wid] = szz; sh[3][wid] = sbb; sh[4][wid] = szb;
        }
        __syncthreads();

        if (threadIdx.x < 32) {
            float a0 = warp_sum(sh[0][lane]);
            float a1 = warp_sum(sh[1][lane]);
            float a2 = warp_sum(sh[2][lane]);
            float a3 = warp_sum(sh[3][lane]);
            float a4 = warp_sum(sh[4][lane]);
            if (lane == 0) {
                g_part[t][0] = a0;
                g_part[t][1] = a1;
                g_part[t][2] = a2;
                g_part[t][3] = a3;
                g_part[t][4] = a4;
            }
        }
        __syncthreads();
    }

    // CTA finished its work; take a completion ticket.
    if (threadIdx.x == 0) {
        __threadfence();
        unsigned int d = atomicAdd(&g_done, 1u);
        s_is_last = (d == GRID - 1u) ? 1 : 0;
    }
    __syncthreads();

    if (s_is_last) {
        __threadfence();  // see all other CTAs' g_part writes
        // Threads 0..255 each assemble one row's corr (fixed combine order).
        __shared__ float shm[THREADS / 32];
        float corr = 0.f;
        if (threadIdx.x < NROWS) {
            const int r = threadIdx.x;
            float a0 = 0.f, a1 = 0.f, a2 = 0.f, a3 = 0.f, a4 = 0.f;
            #pragma unroll
            for (int s = 0; s < SEGS; s++) {
                const int t2 = r * SEGS + s;
                a0 += g_part[t2][0];
                a1 += g_part[t2][1];
                a2 += g_part[t2][2];
                a3 += g_part[t2][3];
                a4 += g_part[t2][4];
            }
            const float invD = 1.0f / (float)D_ELEMS;
            float cov = a4 - a0 * a1 * invD;
            float vz  = fmaxf(a2 - a0 * a0 * invD, 0.f);
            float vb  = fmaxf(a3 - a1 * a1 * invD, 0.f);
            corr = cov / (sqrtf(vz) * sqrtf(vb) + EPS);
        }
        corr = warp_sum(corr);
        if (lane == 0) shm[wid] = corr;
        __syncthreads();
        if (threadIdx.x == 0) {
            float s = 0.f;
            #pragma unroll
            for (int i = 0; i < NROWS / 32; i++) s += shm[i];
            out[0] = s * (1.0f / (float)NROWS);
            g_work = 0;             // reset for next graph replay
            g_done = 0;
            __threadfence();
        }
    }
}

extern "C" void kernel_launch(void* const* d_in, const int* in_sizes, int n_in,
                              void* d_out, int out_size) {
    const float* preds   = (const float*)d_in[0];
    const float* targets = (const float*)d_in[1];
    float* out = (float*)d_out;

    pixcorr_persistent_kernel<<<GRID, THREADS>>>(preds, targets, out);
}